// round 1
// baseline (speedup 1.0000x reference)
#include <cuda_runtime.h>
#include <float.h>

// Problem constants
static constexpr int BB   = 32;
static constexpr int DD   = 64;
static constexpr int HWSZ = 64 * 64;                 // 4096
static constexpr int KK   = 1024;
static constexpr int NPIX = BB * HWSZ;               // 131072
static constexpr int NOUT = NPIX * DD;               // 8388608

// Tiling
static constexpr int P     = 64;   // pixels per block
static constexpr int CHUNK = 64;   // codes per smem chunk
static constexpr int ESTR  = 68;   // padded row stride for es (floats)

__device__ float  g_eSq[KK];
__device__ double g_lossAcc;

__global__ void zero_kernel() { g_lossAcc = 0.0; }

__global__ void esq_kernel(const float* __restrict__ emb) {
    int c = blockIdx.x * blockDim.x + threadIdx.x;
    if (c < KK) {
        const float4* r = (const float4*)(emb + (size_t)c * DD);
        float s = 0.f;
        #pragma unroll
        for (int i = 0; i < DD / 4; i++) {
            float4 v = r[i];
            s += v.x * v.x + v.y * v.y + v.z * v.z + v.w * v.w;
        }
        g_eSq[c] = s;
    }
}

__global__ __launch_bounds__(256)
void vq_kernel(const float* __restrict__ z,
               const float* __restrict__ emb,
               float* __restrict__ out) {
    __shared__ float zs[DD][P];        // 16 KB, [d][p]
    __shared__ float es[CHUNK][ESTR];  // 17 KB, [c][d] padded (reused for output staging)
    __shared__ float eSqS[CHUNK];
    __shared__ int   sIdx[P];
    __shared__ float sMin[P];

    const int tid = threadIdx.x;
    const int tx  = tid & 15;          // code lane (16)
    const int ty  = tid >> 4;          // pixel group (16)

    const int n0  = blockIdx.x * P;
    const int b   = n0 >> 12;          // / 4096
    const int hw0 = n0 & (HWSZ - 1);
    const float* zb = z + (size_t)b * DD * HWSZ + hw0;

    // Stage z tile: [d][p], coalesced (consecutive tid -> consecutive p)
    #pragma unroll
    for (int i = 0; i < (DD * P) / 256; i++) {
        int e = tid + i * 256;
        int d = e >> 6, p = e & (P - 1);
        zs[d][p] = zb[(size_t)d * HWSZ + p];
    }

    float minv[4];
    int   mini[4];
    #pragma unroll
    for (int i = 0; i < 4; i++) { minv[i] = FLT_MAX; mini[i] = 0; }

    for (int c0 = 0; c0 < KK; c0 += CHUNK) {
        __syncthreads();
        // Stage codebook chunk: es[c][d], coalesced float4 copy
        {
            const float4* emb4 = (const float4*)(emb + (size_t)c0 * DD);
            #pragma unroll
            for (int i = 0; i < (CHUNK * DD / 4) / 256; i++) {   // 4
                int f = tid + i * 256;
                int c = f >> 4, dq = f & 15;
                float4 v = emb4[f];
                *(float4*)&es[c][dq * 4] = v;
            }
            if (tid < CHUNK) eSqS[tid] = g_eSq[c0 + tid];
        }
        __syncthreads();

        float acc[4][4];
        #pragma unroll
        for (int i = 0; i < 4; i++)
            #pragma unroll
            for (int j = 0; j < 4; j++) acc[i][j] = 0.f;

        #pragma unroll 4
        for (int dd = 0; dd < DD; dd += 4) {
            float zr[4][4];  // zr[k][i] = zs[dd+k][ty*4+i]
            #pragma unroll
            for (int k = 0; k < 4; k++)
                *(float4*)zr[k] = *(const float4*)&zs[dd + k][ty * 4];
            float er[4][4];  // er[j][k] = es[j*16+tx][dd+k]
            #pragma unroll
            for (int j = 0; j < 4; j++)
                *(float4*)er[j] = *(const float4*)&es[j * 16 + tx][dd];
            #pragma unroll
            for (int i = 0; i < 4; i++)
                #pragma unroll
                for (int j = 0; j < 4; j++)
                    #pragma unroll
                    for (int k = 0; k < 4; k++)
                        acc[i][j] = fmaf(zr[k][i], er[j][k], acc[i][j]);
        }

        // s = ||e||^2 - 2 z.e  (same argmin as full distance)
        #pragma unroll
        for (int j = 0; j < 4; j++) {
            int   c  = c0 + j * 16 + tx;
            float eq = eSqS[j * 16 + tx];
            #pragma unroll
            for (int i = 0; i < 4; i++) {
                float s = fmaf(-2.f, acc[i][j], eq);
                if (s < minv[i] || (s == minv[i] && c < mini[i])) {
                    minv[i] = s; mini[i] = c;
                }
            }
        }
    }

    // Reduce argmin across the 16 code lanes (tx) within each warp
    #pragma unroll
    for (int off = 8; off > 0; off >>= 1) {
        #pragma unroll
        for (int i = 0; i < 4; i++) {
            float ov = __shfl_xor_sync(0xffffffffu, minv[i], off);
            int   oi = __shfl_xor_sync(0xffffffffu, mini[i], off);
            if (ov < minv[i] || (ov == minv[i] && oi < mini[i])) {
                minv[i] = ov; mini[i] = oi;
            }
        }
    }
    if (tx == 0) {
        #pragma unroll
        for (int i = 0; i < 4; i++) {
            sIdx[ty * 4 + i] = mini[i];
            sMin[ty * 4 + i] = minv[i];
        }
    }
    __syncthreads();

    // Loss: per-pixel ||z||^2 + s_min = ||z - e_idx||^2 ; block -> global double
    if (tid < P) {
        int   p   = tid;
        float zq2 = 0.f;
        #pragma unroll
        for (int d = 0; d < DD; d++) zq2 += zs[d][p] * zs[d][p];
        float l = zq2 + sMin[p];
        #pragma unroll
        for (int off = 16; off > 0; off >>= 1)
            l += __shfl_xor_sync(0xffffffffu, l, off);
        if ((tid & 31) == 0) atomicAdd(&g_lossAcc, (double)l);
    }

    // Gather selected code rows into es (reuse), coalesced reads from emb
    #pragma unroll
    for (int i = 0; i < 4; i++) {
        int f = tid + i * 256;
        int p = f >> 4, dq = f & 15;
        float4 v = *(const float4*)(emb + (size_t)sIdx[p] * DD + dq * 4);
        *(float4*)&es[p][dq * 4] = v;
    }
    __syncthreads();

    // Scatter transposed to out[b][d][hw], coalesced global stores
    float* ob = out + (size_t)b * DD * HWSZ + hw0;
    #pragma unroll
    for (int i = 0; i < 16; i++) {
        int e = tid + i * 256;
        int d = e >> 6, p = e & (P - 1);
        ob[(size_t)d * HWSZ + p] = es[p][d];
    }
}

__global__ void fin_kernel(float* __restrict__ out, int pos) {
    if (pos >= 0)
        out[pos] = (float)(1.25 * g_lossAcc / (double)NOUT);
}

extern "C" void kernel_launch(void* const* d_in, const int* in_sizes, int n_in,
                              void* d_out, int out_size) {
    const float* z   = (const float*)d_in[0];
    const float* emb = (const float*)d_in[1];
    float* out = (float*)d_out;

    zero_kernel<<<1, 1>>>();
    esq_kernel<<<(KK + 255) / 256, 256>>>(emb);
    vq_kernel<<<NPIX / P, 256>>>(z, emb, out);
    // Loss scalar lives right after the flattened tensor output (if present)
    int pos = (out_size > NOUT) ? NOUT : -1;
    fin_kernel<<<1, 1>>>(out, pos);
}

// round 3
// speedup vs baseline: 1.0043x; 1.0043x over previous
#include <cuda_runtime.h>
#include <float.h>

// Problem constants
static constexpr int BB   = 32;
static constexpr int DD   = 64;
static constexpr int HWSZ = 64 * 64;                 // 4096
static constexpr int KK   = 1024;
static constexpr int NPIX = BB * HWSZ;               // 131072
static constexpr int NOUT = NPIX * DD;               // 8388608

// Tiling
static constexpr int P     = 64;   // pixels per block
static constexpr int CHUNK = 64;   // codes per smem chunk
static constexpr int ESTR  = 68;   // padded row stride for es (floats)

__device__ float  g_eSq[KK];
__device__ double g_lossAcc;

__global__ void zero_kernel() { g_lossAcc = 0.0; }

__global__ void esq_kernel(const float* __restrict__ emb) {
    int c = blockIdx.x * blockDim.x + threadIdx.x;
    if (c < KK) {
        const float4* r = (const float4*)(emb + (size_t)c * DD);
        float s = 0.f;
        #pragma unroll
        for (int i = 0; i < DD / 4; i++) {
            float4 v = r[i];
            s += v.x * v.x + v.y * v.y + v.z * v.z + v.w * v.w;
        }
        g_eSq[c] = s;
    }
}

__global__ __launch_bounds__(256)
void vq_kernel(const float* __restrict__ z,
               const float* __restrict__ emb,
               float* __restrict__ out) {
    __shared__ float zs[DD][P];        // 16 KB, [d][p]
    __shared__ float es[CHUNK][ESTR];  // 17 KB, [c][d] padded (reused for output staging)
    __shared__ float eSqS[CHUNK];
    __shared__ int   sIdx[P];
    __shared__ float sMin[P];

    const int tid = threadIdx.x;
    const int tx  = tid & 15;          // code lane (16)
    const int ty  = tid >> 4;          // pixel group (16)

    const int n0  = blockIdx.x * P;
    const int b   = n0 >> 12;          // / 4096
    const int hw0 = n0 & (HWSZ - 1);
    const float* zb = z + (size_t)b * DD * HWSZ + hw0;

    // Stage z tile: [d][p], coalesced (consecutive tid -> consecutive p)
    #pragma unroll
    for (int i = 0; i < (DD * P) / 256; i++) {
        int e = tid + i * 256;
        int d = e >> 6, p = e & (P - 1);
        zs[d][p] = zb[(size_t)d * HWSZ + p];
    }

    float minv[4];
    int   mini[4];
    #pragma unroll
    for (int i = 0; i < 4; i++) { minv[i] = FLT_MAX; mini[i] = 0; }

    for (int c0 = 0; c0 < KK; c0 += CHUNK) {
        __syncthreads();
        // Stage codebook chunk: es[c][d], coalesced float4 copy
        {
            const float4* emb4 = (const float4*)(emb + (size_t)c0 * DD);
            #pragma unroll
            for (int i = 0; i < (CHUNK * DD / 4) / 256; i++) {   // 4
                int f = tid + i * 256;
                int c = f >> 4, dq = f & 15;
                float4 v = emb4[f];
                *(float4*)&es[c][dq * 4] = v;
            }
            if (tid < CHUNK) eSqS[tid] = g_eSq[c0 + tid];
        }
        __syncthreads();

        float acc[4][4];
        #pragma unroll
        for (int i = 0; i < 4; i++)
            #pragma unroll
            for (int j = 0; j < 4; j++) acc[i][j] = 0.f;

        #pragma unroll 4
        for (int dd = 0; dd < DD; dd += 4) {
            float zr[4][4];  // zr[k][i] = zs[dd+k][ty*4+i]
            #pragma unroll
            for (int k = 0; k < 4; k++)
                *(float4*)zr[k] = *(const float4*)&zs[dd + k][ty * 4];
            float er[4][4];  // er[j][k] = es[j*16+tx][dd+k]
            #pragma unroll
            for (int j = 0; j < 4; j++)
                *(float4*)er[j] = *(const float4*)&es[j * 16 + tx][dd];
            #pragma unroll
            for (int i = 0; i < 4; i++)
                #pragma unroll
                for (int j = 0; j < 4; j++)
                    #pragma unroll
                    for (int k = 0; k < 4; k++)
                        acc[i][j] = fmaf(zr[k][i], er[j][k], acc[i][j]);
        }

        // s = ||e||^2 - 2 z.e  (same argmin as full distance)
        #pragma unroll
        for (int j = 0; j < 4; j++) {
            int   c  = c0 + j * 16 + tx;
            float eq = eSqS[j * 16 + tx];
            #pragma unroll
            for (int i = 0; i < 4; i++) {
                float s = fmaf(-2.f, acc[i][j], eq);
                if (s < minv[i] || (s == minv[i] && c < mini[i])) {
                    minv[i] = s; mini[i] = c;
                }
            }
        }
    }

    // Reduce argmin across the 16 code lanes (tx) within each warp
    #pragma unroll
    for (int off = 8; off > 0; off >>= 1) {
        #pragma unroll
        for (int i = 0; i < 4; i++) {
            float ov = __shfl_xor_sync(0xffffffffu, minv[i], off);
            int   oi = __shfl_xor_sync(0xffffffffu, mini[i], off);
            if (ov < minv[i] || (ov == minv[i] && oi < mini[i])) {
                minv[i] = ov; mini[i] = oi;
            }
        }
    }
    if (tx == 0) {
        #pragma unroll
        for (int i = 0; i < 4; i++) {
            sIdx[ty * 4 + i] = mini[i];
            sMin[ty * 4 + i] = minv[i];
        }
    }
    __syncthreads();

    // Loss: per-pixel ||z||^2 + s_min = ||z - e_idx||^2 ; block -> global double
    if (tid < P) {
        int   p   = tid;
        float zq2 = 0.f;
        #pragma unroll
        for (int d = 0; d < DD; d++) zq2 += zs[d][p] * zs[d][p];
        float l = zq2 + sMin[p];
        #pragma unroll
        for (int off = 16; off > 0; off >>= 1)
            l += __shfl_xor_sync(0xffffffffu, l, off);
        if ((tid & 31) == 0) atomicAdd(&g_lossAcc, (double)l);
    }

    // Gather selected code rows into es (reuse), coalesced reads from emb
    #pragma unroll
    for (int i = 0; i < 4; i++) {
        int f = tid + i * 256;
        int p = f >> 4, dq = f & 15;
        float4 v = *(const float4*)(emb + (size_t)sIdx[p] * DD + dq * 4);
        *(float4*)&es[p][dq * 4] = v;
    }
    __syncthreads();

    // Scatter transposed to out[b][d][hw], coalesced global stores
    float* ob = out + (size_t)b * DD * HWSZ + hw0;
    #pragma unroll
    for (int i = 0; i < 16; i++) {
        int e = tid + i * 256;
        int d = e >> 6, p = e & (P - 1);
        ob[(size_t)d * HWSZ + p] = es[p][d];
    }
}

__global__ void fin_kernel(float* __restrict__ out, int pos) {
    if (pos >= 0)
        out[pos] = (float)(1.25 * g_lossAcc / (double)NOUT);
}

extern "C" void kernel_launch(void* const* d_in, const int* in_sizes, int n_in,
                              void* d_out, int out_size) {
    const float* z   = (const float*)d_in[0];
    const float* emb = (const float*)d_in[1];
    float* out = (float*)d_out;

    zero_kernel<<<1, 1>>>();
    esq_kernel<<<(KK + 255) / 256, 256>>>(emb);
    vq_kernel<<<NPIX / P, 256>>>(z, emb, out);
    // Loss scalar lives right after the flattened tensor output (if present)
    int pos = (out_size > NOUT) ? NOUT : -1;
    fin_kernel<<<1, 1>>>(out, pos);
}